// round 10
// baseline (speedup 1.0000x reference)
#include <cuda_runtime.h>
#include <cuda_bf16.h>
#include <cstdint>

#define BATCH_TOT 524288
#define KDIM 128
#define NDIM 128
#define CHUNK_ROWS 64
#define NCHUNKS (BATCH_TOT / CHUNK_ROWS)   // 8192

// bf16 tiles, row pitch 272 bytes (17 x 16B) -> conflict-free ldmatrix
#define TPITCH 272
#define WTILE_BYTES (128 * TPITCH)         // 34816
#define XTILE_BYTES (CHUNK_ROWS * TPITCH)  // 17408

// smem layout (bytes)
#define SM_WH   0
#define SM_WL   (SM_WH + WTILE_BYTES)
#define SM_XH   (SM_WL + WTILE_BYTES)
#define SM_XL   (SM_XH + XTILE_BYTES)
#define SM_QUAD (SM_XL + XTILE_BYTES)      // 64 f32
#define SM_SPB  (SM_QUAD + 256)            // 128 f32
#define SM_SPW  (SM_SPB + 512)             // 128 f32
#define SM_TOTAL (SM_SPW + 512)

// global scratch written by prep kernel
__device__ __align__(16) unsigned char g_whi[WTILE_BYTES];
__device__ __align__(16) unsigned char g_wlo[WTILE_BYTES];
__device__ float g_spw[128];
__device__ float g_spb[128];

__device__ __forceinline__ uint32_t smem_u32(const void* p) {
    uint32_t a;
    asm("{ .reg .u64 t; cvta.to.shared.u64 t, %1; cvt.u32.u64 %0, t; }" : "=r"(a) : "l"(p));
    return a;
}
__device__ __forceinline__ void ldsm_x4(uint32_t& r0, uint32_t& r1, uint32_t& r2, uint32_t& r3,
                                        uint32_t addr) {
    asm volatile("ldmatrix.sync.aligned.m8n8.x4.shared.b16 {%0,%1,%2,%3}, [%4];"
                 : "=r"(r0), "=r"(r1), "=r"(r2), "=r"(r3) : "r"(addr));
}
__device__ __forceinline__ void mma_bf16(float* c, const uint32_t* a, uint32_t b0, uint32_t b1) {
    asm volatile(
        "mma.sync.aligned.m16n8k16.row.col.f32.bf16.bf16.f32 "
        "{%0,%1,%2,%3}, {%4,%5,%6,%7}, {%8,%9}, {%0,%1,%2,%3};"
        : "+f"(c[0]), "+f"(c[1]), "+f"(c[2]), "+f"(c[3])
        : "r"(a[0]), "r"(a[1]), "r"(a[2]), "r"(a[3]), "r"(b0), "r"(b1));
}

// ---------- prep: split W -> bf16 hi/lo [n][k] pitch 272, softplus params, KL scalar ----------
__global__ __launch_bounds__(1024)
void prep_kernel(const float* __restrict__ w_mu, const float* __restrict__ w_sigma,
                 const float* __restrict__ b_sigma, float* __restrict__ out_kl)
{
    __shared__ float red[1024];
    const int tid = threadIdx.x;
    float s = 0.f;
    #pragma unroll
    for (int i = 0; i < 16; i++) {
        int idx = tid + i * 1024;            // idx = k*128 + n
        float w = w_mu[idx];
        s += fabsf(w);
        int k = idx >> 7, n = idx & 127;
        __nv_bfloat16 hi = __float2bfloat16(w);
        __nv_bfloat16 lo = __float2bfloat16(w - __bfloat162float(hi));
        int off = n * TPITCH + k * 2;        // B[n][k] = W[k][n]
        *(__nv_bfloat16*)(g_whi + off) = hi;
        *(__nv_bfloat16*)(g_wlo + off) = lo;
    }
    float t = 0.f;
    if (tid < 128) {
        float spw = log1pf(expf(w_sigma[tid]));
        g_spw[tid] = spw;
        t = logf(spw) - spw;                 // 128 * mean_j == sum_j
        g_spb[tid] = log1pf(expf(b_sigma[tid]));
    }
    red[tid] = t - s;
    __syncthreads();
    for (int o = 512; o > 0; o >>= 1) {
        if (tid < o) red[tid] += red[tid + o];
        __syncthreads();
    }
    if (tid == 0) out_kl[0] = -0.5f * red[0];
}

// ---------- fused persistent kernel: 256 threads, W fragments resident in registers ----------
__global__ __launch_bounds__(256, 1)
void fused_kernel(const float* __restrict__ x, const float* __restrict__ b_mu,
                  float* __restrict__ out)
{
    extern __shared__ __align__(16) unsigned char smem[];
    const uint32_t sbase = smem_u32(smem);
    const int tid = threadIdx.x, wid = tid >> 5, lane = tid & 31;

    // ---- one-time: W tiles global->smem, params ----
    {
        const float4* sh = (const float4*)g_whi;
        const float4* sl = (const float4*)g_wlo;
        float4* dh = (float4*)(smem + SM_WH);
        float4* dl = (float4*)(smem + SM_WL);
        #pragma unroll
        for (int i = 0; i < 8; i++) {
            int idx = tid + i * 256;
            dh[idx] = sh[idx];
            dl[idx] = sl[idx];
        }
        if (tid < 128) {
            int idx = 2048 + tid;
            dh[idx] = sh[idx];
            dl[idx] = sl[idx];
        }
    }
    if (tid < 128) {
        ((float*)(smem + SM_SPW))[tid] = g_spw[tid];
        ((float*)(smem + SM_SPB))[tid] = g_spb[tid];
    }

    // warp tile: 32 rows x 32 cols; warps in 2 (m) x 4 (n) grid
    const int m0 = (wid >> 2) * 32;
    const int n0 = (wid & 3) * 32;
    const int g = lane >> 2, tig = lane & 3;

    float2 bm[2][2];
    #pragma unroll
    for (int ni = 0; ni < 2; ni++)
        #pragma unroll
        for (int h = 0; h < 2; h++)
            bm[ni][h] = __ldg((const float2*)(b_mu + n0 + ni * 16 + h * 8 + 2 * tig));

    const uint32_t a_lane = sbase + (uint32_t)((m0 + (lane & 15)) * TPITCH + (lane >> 4) * 16);
    const uint32_t b_lane = sbase + (uint32_t)((n0 + (lane >> 4) * 8 + (lane & 7)) * TPITCH +
                                               ((lane >> 3) & 1) * 16);
    const int row = tid >> 2, quarter = tid & 3;

    __syncthreads();

    // ---- load ALL W fragments into registers (chunk-invariant; kills B-side LDSM traffic) ----
    uint32_t bh[2][8][4], bl[2][8][4];
    #pragma unroll
    for (int ni = 0; ni < 2; ni++)
        #pragma unroll
        for (int kc = 0; kc < 8; kc++) {
            ldsm_x4(bh[ni][kc][0], bh[ni][kc][1], bh[ni][kc][2], bh[ni][kc][3],
                    b_lane + SM_WH + ni * (16 * TPITCH) + kc * 32);
            ldsm_x4(bl[ni][kc][0], bl[ni][kc][1], bl[ni][kc][2], bl[ni][kc][3],
                    b_lane + SM_WL + ni * (16 * TPITCH) + kc * 32);
        }

    for (int chunk = blockIdx.x; chunk < NCHUNKS; chunk += gridDim.x) {
        const size_t rowBase = (size_t)chunk * CHUNK_ROWS;

        // ---- convert x -> xh/xl bf16 tiles + per-row quad (4 threads/row) ----
        {
            const float4* xr = (const float4*)(x + (rowBase + row) * KDIM + quarter * 32);
            const float* spw = (const float*)(smem + SM_SPW) + quarter * 32;
            unsigned char* xh = smem + SM_XH + row * TPITCH + quarter * 64;
            unsigned char* xl = smem + SM_XL + row * TPITCH + quarter * 64;
            float q = 0.f;
            #pragma unroll
            for (int i = 0; i < 8; i++) {
                float4 v = xr[i];
                q = fmaf(v.x * v.x, spw[4 * i + 0], q);
                q = fmaf(v.y * v.y, spw[4 * i + 1], q);
                q = fmaf(v.z * v.z, spw[4 * i + 2], q);
                q = fmaf(v.w * v.w, spw[4 * i + 3], q);
                __nv_bfloat16 h0 = __float2bfloat16(v.x), h1 = __float2bfloat16(v.y);
                __nv_bfloat16 h2 = __float2bfloat16(v.z), h3 = __float2bfloat16(v.w);
                __nv_bfloat16 l0 = __float2bfloat16(v.x - __bfloat162float(h0));
                __nv_bfloat16 l1 = __float2bfloat16(v.y - __bfloat162float(h1));
                __nv_bfloat16 l2 = __float2bfloat16(v.z - __bfloat162float(h2));
                __nv_bfloat16 l3 = __float2bfloat16(v.w - __bfloat162float(h3));
                uint32_t uh0 = ((uint32_t)__bfloat16_as_ushort(h1) << 16) | __bfloat16_as_ushort(h0);
                uint32_t uh1 = ((uint32_t)__bfloat16_as_ushort(h3) << 16) | __bfloat16_as_ushort(h2);
                uint32_t ul0 = ((uint32_t)__bfloat16_as_ushort(l1) << 16) | __bfloat16_as_ushort(l0);
                uint32_t ul1 = ((uint32_t)__bfloat16_as_ushort(l3) << 16) | __bfloat16_as_ushort(l2);
                *(uint2*)(xh + i * 8) = make_uint2(uh0, uh1);
                *(uint2*)(xl + i * 8) = make_uint2(ul0, ul1);
            }
            q += __shfl_xor_sync(0xffffffffu, q, 1);
            q += __shfl_xor_sync(0xffffffffu, q, 2);
            if (quarter == 0) ((float*)(smem + SM_QUAD))[row] = q;
        }
        __syncthreads();

        // ---- GEMM: fused 3-term bf16 split; A from smem, B from registers ----
        float acc[2][2][2][4];                 // [mi][ni][h][4]
        #pragma unroll
        for (int mi = 0; mi < 2; mi++)
            #pragma unroll
            for (int ni = 0; ni < 2; ni++)
                #pragma unroll
                for (int h = 0; h < 2; h++)
                    #pragma unroll
                    for (int j = 0; j < 4; j++) acc[mi][ni][h][j] = 0.f;

        #pragma unroll
        for (int kc = 0; kc < 8; kc++) {
            const uint32_t ko = kc * 32;
            uint32_t ah[2][4], al[2][4];
            #pragma unroll
            for (int mi = 0; mi < 2; mi++) {
                ldsm_x4(ah[mi][0], ah[mi][1], ah[mi][2], ah[mi][3],
                        a_lane + SM_XH + mi * (16 * TPITCH) + ko);
                ldsm_x4(al[mi][0], al[mi][1], al[mi][2], al[mi][3],
                        a_lane + SM_XL + mi * (16 * TPITCH) + ko);
            }
            #pragma unroll
            for (int mi = 0; mi < 2; mi++)
                #pragma unroll
                for (int ni = 0; ni < 2; ni++) {
                    mma_bf16(acc[mi][ni][0], ah[mi], bh[ni][kc][0], bh[ni][kc][1]);  // xh*wh
                    mma_bf16(acc[mi][ni][1], ah[mi], bh[ni][kc][2], bh[ni][kc][3]);
                    mma_bf16(acc[mi][ni][0], al[mi], bh[ni][kc][0], bh[ni][kc][1]);  // xl*wh
                    mma_bf16(acc[mi][ni][1], al[mi], bh[ni][kc][2], bh[ni][kc][3]);
                    mma_bf16(acc[mi][ni][0], ah[mi], bl[ni][kc][0], bl[ni][kc][1]);  // xh*wl
                    mma_bf16(acc[mi][ni][1], ah[mi], bl[ni][kc][2], bl[ni][kc][3]);
                }
        }

        // ---- mu epilogue: fragments -> global ----
        #pragma unroll
        for (int mi = 0; mi < 2; mi++) {
            float* o0 = out + (rowBase + m0 + mi * 16 + g) * NDIM + n0;
            float* o1 = o0 + 8 * NDIM;
            #pragma unroll
            for (int ni = 0; ni < 2; ni++)
                #pragma unroll
                for (int h = 0; h < 2; h++) {
                    const float* c = acc[mi][ni][h];
                    int col = ni * 16 + h * 8 + 2 * tig;
                    float2 b = bm[ni][h];
                    *(float2*)(o0 + col) = make_float2(c[0] + b.x, c[1] + b.y);
                    *(float2*)(o1 + col) = make_float2(c[2] + b.x, c[3] + b.y);
                }
        }

        // ---- sigma epilogue: coalesced float4 ----
        {
            const float* quad = (const float*)(smem + SM_QUAD);
            const float4* spb4 = (const float4*)(smem + SM_SPB);
            float4* sg = (float4*)(out + (size_t)BATCH_TOT * NDIM + rowBase * NDIM);
            #pragma unroll
            for (int i = 0; i < 8; i++) {
                int idx = tid + i * 256;          // 0..2047 float4
                int r = idx >> 5, c4 = idx & 31;
                float q = quad[r];
                float4 s = spb4[c4];
                sg[idx] = make_float4(q + s.x, q + s.y, q + s.z, q + s.w);
            }
        }
        __syncthreads();   // xh/xl/quad reused next chunk
    }
}

extern "C" void kernel_launch(void* const* d_in, const int* in_sizes, int n_in,
                              void* d_out, int out_size)
{
    const float* x       = (const float*)d_in[0];
    const float* w_mu    = (const float*)d_in[1];
    const float* w_sigma = (const float*)d_in[2];
    const float* b_mu    = (const float*)d_in[3];
    const float* b_sigma = (const float*)d_in[4];
    float* out = (float*)d_out;

    int dev = 0, sms = 148;
    cudaGetDevice(&dev);
    cudaDeviceGetAttribute(&sms, cudaDevAttrMultiProcessorCount, dev);
    int grid = sms;                 // 1 persistent CTA per SM (regs-bound)
    if (grid > NCHUNKS) grid = NCHUNKS;

    cudaFuncSetAttribute(fused_kernel, cudaFuncAttributeMaxDynamicSharedMemorySize, SM_TOTAL);

    prep_kernel<<<1, 1024>>>(w_mu, w_sigma, b_sigma, out + (size_t)out_size - 1);
    fused_kernel<<<grid, 256, SM_TOTAL>>>(x, b_mu, out);
}

// round 11
// speedup vs baseline: 1.2886x; 1.2886x over previous
#include <cuda_runtime.h>
#include <cuda_bf16.h>
#include <cstdint>

#define BATCH_TOT 524288
#define KDIM 128
#define NDIM 128
#define CHUNK_ROWS 64
#define NCHUNKS (BATCH_TOT / CHUNK_ROWS)   // 8192

// bf16 tiles, row pitch 272 bytes (17 x 16B) -> conflict-free ldmatrix
#define TPITCH 272
#define WTILE_BYTES (128 * TPITCH)         // 34816
#define XTILE_BYTES (CHUNK_ROWS * TPITCH)  // 17408

// smem layout (bytes)
#define SM_WH   0
#define SM_WL   (SM_WH + WTILE_BYTES)
#define SM_XH   (SM_WL + WTILE_BYTES)
#define SM_XL   (SM_XH + XTILE_BYTES)
#define SM_QUAD (SM_XL + XTILE_BYTES)      // 64 f32
#define SM_SPB  (SM_QUAD + 256)            // 128 f32
#define SM_SPW  (SM_SPB + 512)             // 128 f32
#define SM_TOTAL (SM_SPW + 512)            // 105,728 B -> 2 CTAs/SM

// global scratch written by prep kernel
__device__ __align__(16) unsigned char g_whi[WTILE_BYTES];
__device__ __align__(16) unsigned char g_wlo[WTILE_BYTES];
__device__ float g_spw[128];
__device__ float g_spb[128];

__device__ __forceinline__ uint32_t smem_u32(const void* p) {
    uint32_t a;
    asm("{ .reg .u64 t; cvta.to.shared.u64 t, %1; cvt.u32.u64 %0, t; }" : "=r"(a) : "l"(p));
    return a;
}
__device__ __forceinline__ void ldsm_x4(uint32_t& r0, uint32_t& r1, uint32_t& r2, uint32_t& r3,
                                        uint32_t addr) {
    asm volatile("ldmatrix.sync.aligned.m8n8.x4.shared.b16 {%0,%1,%2,%3}, [%4];"
                 : "=r"(r0), "=r"(r1), "=r"(r2), "=r"(r3) : "r"(addr));
}
__device__ __forceinline__ void mma_bf16(float* c, const uint32_t* a, uint32_t b0, uint32_t b1) {
    asm volatile(
        "mma.sync.aligned.m16n8k16.row.col.f32.bf16.bf16.f32 "
        "{%0,%1,%2,%3}, {%4,%5,%6,%7}, {%8,%9}, {%0,%1,%2,%3};"
        : "+f"(c[0]), "+f"(c[1]), "+f"(c[2]), "+f"(c[3])
        : "r"(a[0]), "r"(a[1]), "r"(a[2]), "r"(a[3]), "r"(b0), "r"(b1));
}

// ---------- prep: split W -> bf16 hi/lo [n][k] pitch 272, softplus params, KL scalar ----------
__global__ __launch_bounds__(1024)
void prep_kernel(const float* __restrict__ w_mu, const float* __restrict__ w_sigma,
                 const float* __restrict__ b_sigma, float* __restrict__ out_kl)
{
    __shared__ float red[1024];
    const int tid = threadIdx.x;
    float s = 0.f;
    #pragma unroll
    for (int i = 0; i < 16; i++) {
        int idx = tid + i * 1024;            // idx = k*128 + n
        float w = w_mu[idx];
        s += fabsf(w);
        int k = idx >> 7, n = idx & 127;
        __nv_bfloat16 hi = __float2bfloat16(w);
        __nv_bfloat16 lo = __float2bfloat16(w - __bfloat162float(hi));
        int off = n * TPITCH + k * 2;        // B[n][k] = W[k][n]
        *(__nv_bfloat16*)(g_whi + off) = hi;
        *(__nv_bfloat16*)(g_wlo + off) = lo;
    }
    float t = 0.f;
    if (tid < 128) {
        float spw = log1pf(expf(w_sigma[tid]));
        g_spw[tid] = spw;
        t = logf(spw) - spw;                 // 128 * mean_j == sum_j
        g_spb[tid] = log1pf(expf(b_sigma[tid]));
    }
    red[tid] = t - s;
    __syncthreads();
    for (int o = 512; o > 0; o >>= 1) {
        if (tid < o) red[tid] += red[tid + o];
        __syncthreads();
    }
    if (tid == 0) out_kl[0] = -0.5f * red[0];
}

// ---------- fused persistent kernel: 128 thr, 2 CTAs/SM, register-prefetched x pipeline --------
__global__ __launch_bounds__(128, 2)
void fused_kernel(const float* __restrict__ x, const float* __restrict__ b_mu,
                  float* __restrict__ out)
{
    extern __shared__ __align__(16) unsigned char smem[];
    const uint32_t sbase = smem_u32(smem);
    const int tid = threadIdx.x, wid = tid >> 5, lane = tid & 31;

    // ---- one-time: W tiles global->smem, params ----
    {
        const float4* sh = (const float4*)g_whi;
        const float4* sl = (const float4*)g_wlo;
        float4* dh = (float4*)(smem + SM_WH);
        float4* dl = (float4*)(smem + SM_WL);
        #pragma unroll
        for (int i = 0; i < 17; i++) {       // 17*128 = 2176 float4
            int idx = tid + i * 128;
            dh[idx] = sh[idx];
            dl[idx] = sl[idx];
        }
    }
    if (tid < 128) {
        ((float*)(smem + SM_SPW))[tid] = g_spw[tid];
        ((float*)(smem + SM_SPB))[tid] = g_spb[tid];
    }

    // warp tile: 32 rows x 64 cols; warps in 2 (m) x 2 (n) grid
    const int m0 = (wid >> 1) * 32;
    const int n0 = (wid & 1) * 64;
    const int g = lane >> 2, tig = lane & 3;

    // b_mu fragment (cols n0 + t*8 + 2*tig), loaded once
    float2 bm[8];
    #pragma unroll
    for (int t = 0; t < 8; t++) bm[t] = __ldg((const float2*)(b_mu + n0 + t * 8 + 2 * tig));

    // ldmatrix lane addresses
    const uint32_t a_lane = sbase + (uint32_t)((m0 + (lane & 15)) * TPITCH + (lane >> 4) * 16);
    const uint32_t b_lane = sbase + (uint32_t)((n0 + (lane >> 4) * 8 + (lane & 7)) * TPITCH +
                                               ((lane >> 3) & 1) * 16);
    const int row = tid >> 1, half = tid & 1;   // convert: 2 threads/row, 64 floats each

    __syncthreads();

    // ---- register prefetch of x for the first chunk ----
    float4 pf[16];
    {
        const float4* xr = (const float4*)(x + ((size_t)blockIdx.x * CHUNK_ROWS + row) * KDIM +
                                           half * 64);
        #pragma unroll
        for (int i = 0; i < 16; i++) pf[i] = xr[i];
    }

    for (int chunk = blockIdx.x; chunk < NCHUNKS; chunk += gridDim.x) {
        const size_t rowBase = (size_t)chunk * CHUNK_ROWS;

        // ---- convert prefetched x -> xh/xl bf16 tiles + per-row quad ----
        {
            const float* spw = (const float*)(smem + SM_SPW) + half * 64;
            unsigned char* xh = smem + SM_XH + row * TPITCH + half * 128;
            unsigned char* xl = smem + SM_XL + row * TPITCH + half * 128;
            float q = 0.f;
            #pragma unroll
            for (int i = 0; i < 16; i++) {
                float4 v = pf[i];
                q = fmaf(v.x * v.x, spw[4 * i + 0], q);
                q = fmaf(v.y * v.y, spw[4 * i + 1], q);
                q = fmaf(v.z * v.z, spw[4 * i + 2], q);
                q = fmaf(v.w * v.w, spw[4 * i + 3], q);
                __nv_bfloat16 h0 = __float2bfloat16(v.x), h1 = __float2bfloat16(v.y);
                __nv_bfloat16 h2 = __float2bfloat16(v.z), h3 = __float2bfloat16(v.w);
                __nv_bfloat16 l0 = __float2bfloat16(v.x - __bfloat162float(h0));
                __nv_bfloat16 l1 = __float2bfloat16(v.y - __bfloat162float(h1));
                __nv_bfloat16 l2 = __float2bfloat16(v.z - __bfloat162float(h2));
                __nv_bfloat16 l3 = __float2bfloat16(v.w - __bfloat162float(h3));
                uint32_t uh0 = ((uint32_t)__bfloat16_as_ushort(h1) << 16) | __bfloat16_as_ushort(h0);
                uint32_t uh1 = ((uint32_t)__bfloat16_as_ushort(h3) << 16) | __bfloat16_as_ushort(h2);
                uint32_t ul0 = ((uint32_t)__bfloat16_as_ushort(l1) << 16) | __bfloat16_as_ushort(l0);
                uint32_t ul1 = ((uint32_t)__bfloat16_as_ushort(l3) << 16) | __bfloat16_as_ushort(l2);
                *(uint2*)(xh + i * 8) = make_uint2(uh0, uh1);
                *(uint2*)(xl + i * 8) = make_uint2(ul0, ul1);
            }
            q += __shfl_xor_sync(0xffffffffu, q, 1);
            if (half == 0) ((float*)(smem + SM_QUAD))[row] = q;
        }

        // ---- issue prefetch for the NEXT chunk (covered by GEMM + epilogue latency) ----
        {
            int nextc = chunk + gridDim.x;
            if (nextc < NCHUNKS) {
                const float4* xr = (const float4*)(x + ((size_t)nextc * CHUNK_ROWS + row) * KDIM +
                                                   half * 64);
                #pragma unroll
                for (int i = 0; i < 16; i++) pf[i] = xr[i];
            }
        }
        __syncthreads();

        // ---- GEMM: fused 3-term bf16 split, 32x64 warp tile ----
        float acc[2][4][2][4];                 // [mi][ni][h][4]
        #pragma unroll
        for (int mi = 0; mi < 2; mi++)
            #pragma unroll
            for (int ni = 0; ni < 4; ni++)
                #pragma unroll
                for (int h = 0; h < 2; h++)
                    #pragma unroll
                    for (int j = 0; j < 4; j++) acc[mi][ni][h][j] = 0.f;

        #pragma unroll
        for (int kc = 0; kc < 8; kc++) {
            const uint32_t ko = kc * 32;
            uint32_t ah[2][4], al[2][4], bh[4][4], bl[4][4];
            #pragma unroll
            for (int mi = 0; mi < 2; mi++) {
                ldsm_x4(ah[mi][0], ah[mi][1], ah[mi][2], ah[mi][3],
                        a_lane + SM_XH + mi * (16 * TPITCH) + ko);
                ldsm_x4(al[mi][0], al[mi][1], al[mi][2], al[mi][3],
                        a_lane + SM_XL + mi * (16 * TPITCH) + ko);
            }
            #pragma unroll
            for (int ni = 0; ni < 4; ni++) {
                ldsm_x4(bh[ni][0], bh[ni][1], bh[ni][2], bh[ni][3],
                        b_lane + SM_WH + ni * (16 * TPITCH) + ko);
                ldsm_x4(bl[ni][0], bl[ni][1], bl[ni][2], bl[ni][3],
                        b_lane + SM_WL + ni * (16 * TPITCH) + ko);
            }
            #pragma unroll
            for (int mi = 0; mi < 2; mi++)
                #pragma unroll
                for (int ni = 0; ni < 4; ni++) {
                    mma_bf16(acc[mi][ni][0], ah[mi], bh[ni][0], bh[ni][1]);  // xh*wh
                    mma_bf16(acc[mi][ni][1], ah[mi], bh[ni][2], bh[ni][3]);
                    mma_bf16(acc[mi][ni][0], al[mi], bh[ni][0], bh[ni][1]);  // xl*wh
                    mma_bf16(acc[mi][ni][1], al[mi], bh[ni][2], bh[ni][3]);
                    mma_bf16(acc[mi][ni][0], ah[mi], bl[ni][0], bl[ni][1]);  // xh*wl
                    mma_bf16(acc[mi][ni][1], ah[mi], bl[ni][2], bl[ni][3]);
                }
        }

        // ---- mu epilogue: fragments -> global ----
        #pragma unroll
        for (int mi = 0; mi < 2; mi++) {
            float* o0 = out + (rowBase + m0 + mi * 16 + g) * NDIM + n0;
            float* o1 = o0 + 8 * NDIM;
            #pragma unroll
            for (int ni = 0; ni < 4; ni++)
                #pragma unroll
                for (int h = 0; h < 2; h++) {
                    const float* c = acc[mi][ni][h];
                    int col = ni * 16 + h * 8 + 2 * tig;
                    float2 b = bm[ni * 2 + h];
                    *(float2*)(o0 + col) = make_float2(c[0] + b.x, c[1] + b.y);
                    *(float2*)(o1 + col) = make_float2(c[2] + b.x, c[3] + b.y);
                }
        }

        // ---- sigma epilogue: coalesced float4 ----
        {
            const float* quad = (const float*)(smem + SM_QUAD);
            const float4* spb4 = (const float4*)(smem + SM_SPB);
            float4* sg = (float4*)(out + (size_t)BATCH_TOT * NDIM + rowBase * NDIM);
            #pragma unroll
            for (int i = 0; i < 16; i++) {
                int idx = tid + i * 128;          // 0..2047 float4
                int r = idx >> 5, c4 = idx & 31;
                float q = quad[r];
                float4 s = spb4[c4];
                sg[idx] = make_float4(q + s.x, q + s.y, q + s.z, q + s.w);
            }
        }
        __syncthreads();   // xh/xl/quad reused next chunk
    }
}

extern "C" void kernel_launch(void* const* d_in, const int* in_sizes, int n_in,
                              void* d_out, int out_size)
{
    const float* x       = (const float*)d_in[0];
    const float* w_mu    = (const float*)d_in[1];
    const float* w_sigma = (const float*)d_in[2];
    const float* b_mu    = (const float*)d_in[3];
    const float* b_sigma = (const float*)d_in[4];
    float* out = (float*)d_out;

    int dev = 0, sms = 148;
    cudaGetDevice(&dev);
    cudaDeviceGetAttribute(&sms, cudaDevAttrMultiProcessorCount, dev);
    int grid = 2 * sms;
    if (grid > NCHUNKS) grid = NCHUNKS;

    cudaFuncSetAttribute(fused_kernel, cudaFuncAttributeMaxDynamicSharedMemorySize, SM_TOTAL);

    prep_kernel<<<1, 1024>>>(w_mu, w_sigma, b_sigma, out + (size_t)out_size - 1);
    fused_kernel<<<grid, 128, SM_TOTAL>>>(x, b_mu, out);
}

// round 15
// speedup vs baseline: 1.4555x; 1.1296x over previous
#include <cuda_runtime.h>
#include <cuda_bf16.h>
#include <cstdint>

#define BATCH_TOT 524288
#define KDIM 128
#define NDIM 128
#define CHUNK_ROWS 64
#define NCHUNKS (BATCH_TOT / CHUNK_ROWS)   // 8192

// bf16 tiles, row pitch 272 bytes (17 x 16B) -> conflict-free ldmatrix
#define TPITCH 272
#define WTILE_BYTES (128 * TPITCH)         // 34816
#define XTILE_BYTES (CHUNK_ROWS * TPITCH)  // 17408

// smem layout (bytes)
#define SM_WH   0
#define SM_WL   (SM_WH + WTILE_BYTES)
#define SM_XH   (SM_WL + WTILE_BYTES)
#define SM_XL   (SM_XH + XTILE_BYTES)
#define SM_QUAD (SM_XL + XTILE_BYTES)      // 64 f32
#define SM_SPB  (SM_QUAD + 256)            // 128 f32
#define SM_SPW  (SM_SPB + 512)             // 128 f32
#define SM_RED  (SM_SPW + 512)             // 4 f32 (KL warp partials, CTA 0)
#define SM_TOTAL (SM_RED + 64)             // ~105.8 KB -> 2 CTAs/SM

__device__ __forceinline__ uint32_t smem_u32(const void* p) {
    uint32_t a;
    asm("{ .reg .u64 t; cvta.to.shared.u64 t, %1; cvt.u32.u64 %0, t; }" : "=r"(a) : "l"(p));
    return a;
}
__device__ __forceinline__ void ldsm_x4(uint32_t& r0, uint32_t& r1, uint32_t& r2, uint32_t& r3,
                                        uint32_t addr) {
    asm volatile("ldmatrix.sync.aligned.m8n8.x4.shared.b16 {%0,%1,%2,%3}, [%4];"
                 : "=r"(r0), "=r"(r1), "=r"(r2), "=r"(r3) : "r"(addr));
}
__device__ __forceinline__ void mma_bf16(float* c, const uint32_t* a, uint32_t b0, uint32_t b1) {
    asm volatile(
        "mma.sync.aligned.m16n8k16.row.col.f32.bf16.bf16.f32 "
        "{%0,%1,%2,%3}, {%4,%5,%6,%7}, {%8,%9}, {%0,%1,%2,%3};"
        : "+f"(c[0]), "+f"(c[1]), "+f"(c[2]), "+f"(c[3])
        : "r"(a[0]), "r"(a[1]), "r"(a[2]), "r"(a[3]), "r"(b0), "r"(b1));
}

// ---------- single fused persistent kernel: W split + KL inline, no prep launch ----------
__global__ __launch_bounds__(128, 2)
void fused_kernel(const float* __restrict__ x, const float* __restrict__ w_mu,
                  const float* __restrict__ w_sigma, const float* __restrict__ b_mu,
                  const float* __restrict__ b_sigma, float* __restrict__ out,
                  float* __restrict__ out_kl)
{
    extern __shared__ __align__(16) unsigned char smem[];
    const uint32_t sbase = smem_u32(smem);
    const int tid = threadIdx.x, wid = tid >> 5, lane = tid & 31;

    // ---- one-time: softplus params ----
    if (tid < 128) {
        float spw = log1pf(expf(w_sigma[tid]));
        ((float*)(smem + SM_SPW))[tid] = spw;
        ((float*)(smem + SM_SPB))[tid] = log1pf(expf(b_sigma[tid]));
    }

    // ---- one-time: split W -> bf16 hi/lo directly into smem; accumulate |w| for KL ----
    float wabs = 0.f;
    #pragma unroll
    for (int i = 0; i < 128; i++) {
        int idx = tid + i * 128;             // idx = k*128 + n
        float w = w_mu[idx];
        wabs += fabsf(w);
        int k = idx >> 7, n = idx & 127;
        __nv_bfloat16 hi = __float2bfloat16(w);
        __nv_bfloat16 lo = __float2bfloat16(w - __bfloat162float(hi));
        int off = n * TPITCH + k * 2;        // B[n][k] = W[k][n]
        *(__nv_bfloat16*)(smem + SM_WH + off) = hi;
        *(__nv_bfloat16*)(smem + SM_WL + off) = lo;
    }
    if (blockIdx.x == 0) {
        // warp shuffle reduction of wabs, then 4 partials -> thread 0
        #pragma unroll
        for (int o = 16; o > 0; o >>= 1) wabs += __shfl_xor_sync(0xffffffffu, wabs, o);
        if (lane == 0) ((float*)(smem + SM_RED))[wid] = wabs;
        __syncthreads();
        if (tid == 0) {
            const float* red = (const float*)(smem + SM_RED);
            const float* spw = (const float*)(smem + SM_SPW);
            float s = red[0] + red[1] + red[2] + red[3];
            float t = 0.f;
            #pragma unroll
            for (int j = 0; j < 128; j++) t += logf(spw[j]) - spw[j];
            // kl = -0.5 * mean_j(128*log spw_j - s - 128*spw_j) = -0.5 * (sum_j(log spw_j - spw_j) - s)
            out_kl[0] = -0.5f * (t - s);
        }
    }

    // warp tile: 32 rows x 64 cols; warps in 2 (m) x 2 (n) grid
    const int m0 = (wid >> 1) * 32;
    const int n0 = (wid & 1) * 64;
    const int g = lane >> 2, tig = lane & 3;

    float2 bm[8];
    #pragma unroll
    for (int t = 0; t < 8; t++) bm[t] = __ldg((const float2*)(b_mu + n0 + t * 8 + 2 * tig));

    const uint32_t a_lane = sbase + (uint32_t)((m0 + (lane & 15)) * TPITCH + (lane >> 4) * 16);
    const uint32_t b_lane = sbase + (uint32_t)((n0 + (lane >> 4) * 8 + (lane & 7)) * TPITCH +
                                               ((lane >> 3) & 1) * 16);
    const int row = tid >> 1, half = tid & 1;

    __syncthreads();

    // ---- register prefetch of x for the first chunk ----
    float4 pf[16];
    {
        const float4* xr = (const float4*)(x + ((size_t)blockIdx.x * CHUNK_ROWS + row) * KDIM +
                                           half * 64);
        #pragma unroll
        for (int i = 0; i < 16; i++) pf[i] = xr[i];
    }

    for (int chunk = blockIdx.x; chunk < NCHUNKS; chunk += gridDim.x) {
        const size_t rowBase = (size_t)chunk * CHUNK_ROWS;

        // ---- convert prefetched x -> xh/xl bf16 tiles + per-row quad ----
        {
            const float* spw = (const float*)(smem + SM_SPW) + half * 64;
            unsigned char* xh = smem + SM_XH + row * TPITCH + half * 128;
            unsigned char* xl = smem + SM_XL + row * TPITCH + half * 128;
            float q = 0.f;
            #pragma unroll
            for (int i = 0; i < 16; i++) {
                float4 v = pf[i];
                q = fmaf(v.x * v.x, spw[4 * i + 0], q);
                q = fmaf(v.y * v.y, spw[4 * i + 1], q);
                q = fmaf(v.z * v.z, spw[4 * i + 2], q);
                q = fmaf(v.w * v.w, spw[4 * i + 3], q);
                __nv_bfloat16 h0 = __float2bfloat16(v.x), h1 = __float2bfloat16(v.y);
                __nv_bfloat16 h2 = __float2bfloat16(v.z), h3 = __float2bfloat16(v.w);
                __nv_bfloat16 l0 = __float2bfloat16(v.x - __bfloat162float(h0));
                __nv_bfloat16 l1 = __float2bfloat16(v.y - __bfloat162float(h1));
                __nv_bfloat16 l2 = __float2bfloat16(v.z - __bfloat162float(h2));
                __nv_bfloat16 l3 = __float2bfloat16(v.w - __bfloat162float(h3));
                uint32_t uh0 = ((uint32_t)__bfloat16_as_ushort(h1) << 16) | __bfloat16_as_ushort(h0);
                uint32_t uh1 = ((uint32_t)__bfloat16_as_ushort(h3) << 16) | __bfloat16_as_ushort(h2);
                uint32_t ul0 = ((uint32_t)__bfloat16_as_ushort(l1) << 16) | __bfloat16_as_ushort(l0);
                uint32_t ul1 = ((uint32_t)__bfloat16_as_ushort(l3) << 16) | __bfloat16_as_ushort(l2);
                *(uint2*)(xh + i * 8) = make_uint2(uh0, uh1);
                *(uint2*)(xl + i * 8) = make_uint2(ul0, ul1);
            }
            q += __shfl_xor_sync(0xffffffffu, q, 1);
            if (half == 0) ((float*)(smem + SM_QUAD))[row] = q;
        }

        // ---- issue prefetch for the NEXT chunk (covered by GEMM + epilogue latency) ----
        {
            int nextc = chunk + gridDim.x;
            if (nextc < NCHUNKS) {
                const float4* xr = (const float4*)(x + ((size_t)nextc * CHUNK_ROWS + row) * KDIM +
                                                   half * 64);
                #pragma unroll
                for (int i = 0; i < 16; i++) pf[i] = xr[i];
            }
        }
        __syncthreads();

        // ---- GEMM: fused 3-term bf16 split, 32x64 warp tile ----
        float acc[2][4][2][4];                 // [mi][ni][h][4]
        #pragma unroll
        for (int mi = 0; mi < 2; mi++)
            #pragma unroll
            for (int ni = 0; ni < 4; ni++)
                #pragma unroll
                for (int h = 0; h < 2; h++)
                    #pragma unroll
                    for (int j = 0; j < 4; j++) acc[mi][ni][h][j] = 0.f;

        #pragma unroll
        for (int kc = 0; kc < 8; kc++) {
            const uint32_t ko = kc * 32;
            uint32_t ah[2][4], al[2][4], bh[4][4], bl[4][4];
            #pragma unroll
            for (int mi = 0; mi < 2; mi++) {
                ldsm_x4(ah[mi][0], ah[mi][1], ah[mi][2], ah[mi][3],
                        a_lane + SM_XH + mi * (16 * TPITCH) + ko);
                ldsm_x4(al[mi][0], al[mi][1], al[mi][2], al[mi][3],
                        a_lane + SM_XL + mi * (16 * TPITCH) + ko);
            }
            #pragma unroll
            for (int ni = 0; ni < 4; ni++) {
                ldsm_x4(bh[ni][0], bh[ni][1], bh[ni][2], bh[ni][3],
                        b_lane + SM_WH + ni * (16 * TPITCH) + ko);
                ldsm_x4(bl[ni][0], bl[ni][1], bl[ni][2], bl[ni][3],
                        b_lane + SM_WL + ni * (16 * TPITCH) + ko);
            }
            #pragma unroll
            for (int mi = 0; mi < 2; mi++)
                #pragma unroll
                for (int ni = 0; ni < 4; ni++) {
                    mma_bf16(acc[mi][ni][0], ah[mi], bh[ni][0], bh[ni][1]);  // xh*wh
                    mma_bf16(acc[mi][ni][1], ah[mi], bh[ni][2], bh[ni][3]);
                    mma_bf16(acc[mi][ni][0], al[mi], bh[ni][0], bh[ni][1]);  // xl*wh
                    mma_bf16(acc[mi][ni][1], al[mi], bh[ni][2], bh[ni][3]);
                    mma_bf16(acc[mi][ni][0], ah[mi], bl[ni][0], bl[ni][1]);  // xh*wl
                    mma_bf16(acc[mi][ni][1], ah[mi], bl[ni][2], bl[ni][3]);
                }
        }

        // ---- mu epilogue: fragments -> global ----
        #pragma unroll
        for (int mi = 0; mi < 2; mi++) {
            float* o0 = out + (rowBase + m0 + mi * 16 + g) * NDIM + n0;
            float* o1 = o0 + 8 * NDIM;
            #pragma unroll
            for (int ni = 0; ni < 4; ni++)
                #pragma unroll
                for (int h = 0; h < 2; h++) {
                    const float* c = acc[mi][ni][h];
                    int col = ni * 16 + h * 8 + 2 * tig;
                    float2 b = bm[ni * 2 + h];
                    *(float2*)(o0 + col) = make_float2(c[0] + b.x, c[1] + b.y);
                    *(float2*)(o1 + col) = make_float2(c[2] + b.x, c[3] + b.y);
                }
        }

        // ---- sigma epilogue: coalesced float4 ----
        {
            const float* quad = (const float*)(smem + SM_QUAD);
            const float4* spb4 = (const float4*)(smem + SM_SPB);
            float4* sg = (float4*)(out + (size_t)BATCH_TOT * NDIM + rowBase * NDIM);
            #pragma unroll
            for (int i = 0; i < 16; i++) {
                int idx = tid + i * 128;          // 0..2047 float4
                int r = idx >> 5, c4 = idx & 31;
                float q = quad[r];
                float4 s = spb4[c4];
                sg[idx] = make_float4(q + s.x, q + s.y, q + s.z, q + s.w);
            }
        }
        __syncthreads();   // xh/xl/quad reused next chunk
    }
}

extern "C" void kernel_launch(void* const* d_in, const int* in_sizes, int n_in,
                              void* d_out, int out_size)
{
    const float* x       = (const float*)d_in[0];
    const float* w_mu    = (const float*)d_in[1];
    const float* w_sigma = (const float*)d_in[2];
    const float* b_mu    = (const float*)d_in[3];
    const float* b_sigma = (const float*)d_in[4];
    float* out = (float*)d_out;

    int dev = 0, sms = 148;
    cudaGetDevice(&dev);
    cudaDeviceGetAttribute(&sms, cudaDevAttrMultiProcessorCount, dev);
    int grid = 2 * sms;
    if (grid > NCHUNKS) grid = NCHUNKS;

    cudaFuncSetAttribute(fused_kernel, cudaFuncAttributeMaxDynamicSharedMemorySize, SM_TOTAL);

    fused_kernel<<<grid, 128, SM_TOTAL>>>(x, w_mu, w_sigma, b_mu, b_sigma, out,
                                          out + (size_t)out_size - 1);
}

// round 16
// speedup vs baseline: 1.5566x; 1.0694x over previous
#include <cuda_runtime.h>
#include <cuda_bf16.h>
#include <cstdint>

#define BATCH_TOT 524288
#define KDIM 128
#define NDIM 128
#define CHUNK_ROWS 64
#define NCHUNKS (BATCH_TOT / CHUNK_ROWS)   // 8192

// bf16 tiles, row pitch 272 bytes (17 x 16B) -> conflict-free ldmatrix
#define TPITCH 272
#define WTILE_BYTES (128 * TPITCH)         // 34816
#define XTILE_BYTES (CHUNK_ROWS * TPITCH)  // 17408

// smem layout (bytes)
#define SM_WH   0
#define SM_WL   (SM_WH + WTILE_BYTES)
#define SM_XH   (SM_WL + WTILE_BYTES)
#define SM_XL   (SM_XH + XTILE_BYTES)
#define SM_QUAD (SM_XL + XTILE_BYTES)      // 64 f32
#define SM_SPB  (SM_QUAD + 256)            // 128 f32
#define SM_SPW  (SM_SPB + 512)             // 128 f32
#define SM_RED  (SM_SPW + 512)             // 4 f32 (KL warp partials, CTA 0)
#define SM_TOTAL (SM_RED + 64)             // ~105.8 KB -> 2 CTAs/SM

__device__ __forceinline__ uint32_t smem_u32(const void* p) {
    uint32_t a;
    asm("{ .reg .u64 t; cvta.to.shared.u64 t, %1; cvt.u32.u64 %0, t; }" : "=r"(a) : "l"(p));
    return a;
}
__device__ __forceinline__ void ldsm_x4(uint32_t& r0, uint32_t& r1, uint32_t& r2, uint32_t& r3,
                                        uint32_t addr) {
    asm volatile("ldmatrix.sync.aligned.m8n8.x4.shared.b16 {%0,%1,%2,%3}, [%4];"
                 : "=r"(r0), "=r"(r1), "=r"(r2), "=r"(r3) : "r"(addr));
}
__device__ __forceinline__ void mma_bf16(float* c, const uint32_t* a, uint32_t b0, uint32_t b1) {
    asm volatile(
        "mma.sync.aligned.m16n8k16.row.col.f32.bf16.bf16.f32 "
        "{%0,%1,%2,%3}, {%4,%5,%6,%7}, {%8,%9}, {%0,%1,%2,%3};"
        : "+f"(c[0]), "+f"(c[1]), "+f"(c[2]), "+f"(c[3])
        : "r"(a[0]), "r"(a[1]), "r"(a[2]), "r"(a[3]), "r"(b0), "r"(b1));
}
__device__ __forceinline__ void bar_pair(int id) {
    asm volatile("bar.sync %0, 64;" :: "r"(id) : "memory");
}

// ---------- single fused persistent kernel: W split + KL inline; warp-pair pipelines ----------
__global__ __launch_bounds__(128, 2)
void fused_kernel(const float* __restrict__ x, const float* __restrict__ w_mu,
                  const float* __restrict__ w_sigma, const float* __restrict__ b_mu,
                  const float* __restrict__ b_sigma, float* __restrict__ out,
                  float* __restrict__ out_kl)
{
    extern __shared__ __align__(16) unsigned char smem[];
    const uint32_t sbase = smem_u32(smem);
    const int tid = threadIdx.x, wid = tid >> 5, lane = tid & 31;
    const int pair = wid >> 1;                // 0: rows 0-31, 1: rows 32-63
    const int ptid = tid & 63;                // thread id within pair

    // ---- one-time: softplus params ----
    if (tid < 128) {
        float spw = log1pf(expf(w_sigma[tid]));
        ((float*)(smem + SM_SPW))[tid] = spw;
        ((float*)(smem + SM_SPB))[tid] = log1pf(expf(b_sigma[tid]));
    }

    // ---- one-time: split W -> bf16 hi/lo directly into smem; accumulate |w| for KL ----
    float wabs = 0.f;
    #pragma unroll
    for (int i = 0; i < 128; i++) {
        int idx = tid + i * 128;             // idx = k*128 + n
        float w = w_mu[idx];
        wabs += fabsf(w);
        int k = idx >> 7, n = idx & 127;
        __nv_bfloat16 hi = __float2bfloat16(w);
        __nv_bfloat16 lo = __float2bfloat16(w - __bfloat162float(hi));
        int off = n * TPITCH + k * 2;        // B[n][k] = W[k][n]
        *(__nv_bfloat16*)(smem + SM_WH + off) = hi;
        *(__nv_bfloat16*)(smem + SM_WL + off) = lo;
    }
    if (blockIdx.x == 0) {
        #pragma unroll
        for (int o = 16; o > 0; o >>= 1) wabs += __shfl_xor_sync(0xffffffffu, wabs, o);
        if (lane == 0) ((float*)(smem + SM_RED))[wid] = wabs;
        __syncthreads();
        if (tid == 0) {
            const float* red = (const float*)(smem + SM_RED);
            const float* spw = (const float*)(smem + SM_SPW);
            float s = red[0] + red[1] + red[2] + red[3];
            float t = 0.f;
            #pragma unroll
            for (int j = 0; j < 128; j++) t += logf(spw[j]) - spw[j];
            out_kl[0] = -0.5f * (t - s);
        }
    }

    // GEMM warp tile: 32 rows x 64 cols; warps {0,1}->rows 0-31, {2,3}->rows 32-63
    const int m0 = pair * 32;
    const int n0 = (wid & 1) * 64;
    const int g = lane >> 2, tig = lane & 3;

    float2 bm[8];
    #pragma unroll
    for (int t = 0; t < 8; t++) bm[t] = __ldg((const float2*)(b_mu + n0 + t * 8 + 2 * tig));

    const uint32_t a_lane = sbase + (uint32_t)((m0 + (lane & 15)) * TPITCH + (lane >> 4) * 16);
    const uint32_t b_lane = sbase + (uint32_t)((n0 + (lane >> 4) * 8 + (lane & 7)) * TPITCH +
                                               ((lane >> 3) & 1) * 16);
    // convert mapping: pair-local, 2 threads per row
    const int crow = m0 + (ptid >> 1);        // row within chunk, owned by this pair
    const int half = ptid & 1;

    __syncthreads();                          // prologue fence (W + params visible)

    // ---- register prefetch of x for the first chunk ----
    float4 pf[16];
    {
        const float4* xr = (const float4*)(x + ((size_t)blockIdx.x * CHUNK_ROWS + crow) * KDIM +
                                           half * 64);
        #pragma unroll
        for (int i = 0; i < 16; i++) pf[i] = xr[i];
    }

    for (int chunk = blockIdx.x; chunk < NCHUNKS; chunk += gridDim.x) {
        const size_t rowBase = (size_t)chunk * CHUNK_ROWS;

        // ---- convert prefetched x -> xh/xl bf16 tiles + per-row quad (pair-local rows) ----
        {
            const float* spw = (const float*)(smem + SM_SPW) + half * 64;
            unsigned char* xh = smem + SM_XH + crow * TPITCH + half * 128;
            unsigned char* xl = smem + SM_XL + crow * TPITCH + half * 128;
            float q = 0.f;
            #pragma unroll
            for (int i = 0; i < 16; i++) {
                float4 v = pf[i];
                q = fmaf(v.x * v.x, spw[4 * i + 0], q);
                q = fmaf(v.y * v.y, spw[4 * i + 1], q);
                q = fmaf(v.z * v.z, spw[4 * i + 2], q);
                q = fmaf(v.w * v.w, spw[4 * i + 3], q);
                __nv_bfloat16 h0 = __float2bfloat16(v.x), h1 = __float2bfloat16(v.y);
                __nv_bfloat16 h2 = __float2bfloat16(v.z), h3 = __float2bfloat16(v.w);
                __nv_bfloat16 l0 = __float2bfloat16(v.x - __bfloat162float(h0));
                __nv_bfloat16 l1 = __float2bfloat16(v.y - __bfloat162float(h1));
                __nv_bfloat16 l2 = __float2bfloat16(v.z - __bfloat162float(h2));
                __nv_bfloat16 l3 = __float2bfloat16(v.w - __bfloat162float(h3));
                uint32_t uh0 = ((uint32_t)__bfloat16_as_ushort(h1) << 16) | __bfloat16_as_ushort(h0);
                uint32_t uh1 = ((uint32_t)__bfloat16_as_ushort(h3) << 16) | __bfloat16_as_ushort(h2);
                uint32_t ul0 = ((uint32_t)__bfloat16_as_ushort(l1) << 16) | __bfloat16_as_ushort(l0);
                uint32_t ul1 = ((uint32_t)__bfloat16_as_ushort(l3) << 16) | __bfloat16_as_ushort(l2);
                *(uint2*)(xh + i * 8) = make_uint2(uh0, uh1);
                *(uint2*)(xl + i * 8) = make_uint2(ul0, ul1);
            }
            q += __shfl_xor_sync(0xffffffffu, q, 1);
            if (half == 0) ((float*)(smem + SM_QUAD))[crow] = q;
        }

        // ---- issue prefetch for the NEXT chunk (covered by GEMM + epilogue latency) ----
        {
            int nextc = chunk + gridDim.x;
            if (nextc < NCHUNKS) {
                const float4* xr = (const float4*)(x + ((size_t)nextc * CHUNK_ROWS + crow) * KDIM +
                                                   half * 64);
                #pragma unroll
                for (int i = 0; i < 16; i++) pf[i] = xr[i];
            }
        }
        bar_pair(pair + 1);                   // pair-scoped: our 32 rows of xh/xl/quad ready

        // ---- GEMM: fused 3-term bf16 split, 32x64 warp tile ----
        float acc[2][4][2][4];                 // [mi][ni][h][4]
        #pragma unroll
        for (int mi = 0; mi < 2; mi++)
            #pragma unroll
            for (int ni = 0; ni < 4; ni++)
                #pragma unroll
                for (int h = 0; h < 2; h++)
                    #pragma unroll
                    for (int j = 0; j < 4; j++) acc[mi][ni][h][j] = 0.f;

        #pragma unroll
        for (int kc = 0; kc < 8; kc++) {
            const uint32_t ko = kc * 32;
            uint32_t ah[2][4], al[2][4], bh[4][4], bl[4][4];
            #pragma unroll
            for (int mi = 0; mi < 2; mi++) {
                ldsm_x4(ah[mi][0], ah[mi][1], ah[mi][2], ah[mi][3],
                        a_lane + SM_XH + mi * (16 * TPITCH) + ko);
                ldsm_x4(al[mi][0], al[mi][1], al[mi][2], al[mi][3],
                        a_lane + SM_XL + mi * (16 * TPITCH) + ko);
            }
            #pragma unroll
            for (int ni = 0; ni < 4; ni++) {
                ldsm_x4(bh[ni][0], bh[ni][1], bh[ni][2], bh[ni][3],
                        b_lane + SM_WH + ni * (16 * TPITCH) + ko);
                ldsm_x4(bl[ni][0], bl[ni][1], bl[ni][2], bl[ni][3],
                        b_lane + SM_WL + ni * (16 * TPITCH) + ko);
            }
            #pragma unroll
            for (int mi = 0; mi < 2; mi++)
                #pragma unroll
                for (int ni = 0; ni < 4; ni++) {
                    mma_bf16(acc[mi][ni][0], ah[mi], bh[ni][0], bh[ni][1]);  // xh*wh
                    mma_bf16(acc[mi][ni][1], ah[mi], bh[ni][2], bh[ni][3]);
                    mma_bf16(acc[mi][ni][0], al[mi], bh[ni][0], bh[ni][1]);  // xl*wh
                    mma_bf16(acc[mi][ni][1], al[mi], bh[ni][2], bh[ni][3]);
                    mma_bf16(acc[mi][ni][0], ah[mi], bl[ni][0], bl[ni][1]);  // xh*wl
                    mma_bf16(acc[mi][ni][1], ah[mi], bl[ni][2], bl[ni][3]);
                }
        }

        // ---- mu epilogue: fragments -> global ----
        #pragma unroll
        for (int mi = 0; mi < 2; mi++) {
            float* o0 = out + (rowBase + m0 + mi * 16 + g) * NDIM + n0;
            float* o1 = o0 + 8 * NDIM;
            #pragma unroll
            for (int ni = 0; ni < 4; ni++)
                #pragma unroll
                for (int h = 0; h < 2; h++) {
                    const float* c = acc[mi][ni][h];
                    int col = ni * 16 + h * 8 + 2 * tig;
                    float2 b = bm[ni * 2 + h];
                    *(float2*)(o0 + col) = make_float2(c[0] + b.x, c[1] + b.y);
                    *(float2*)(o1 + col) = make_float2(c[2] + b.x, c[3] + b.y);
                }
        }

        // ---- sigma epilogue: pair-local rows, coalesced float4 ----
        {
            const float* quad = (const float*)(smem + SM_QUAD);
            const float4* spb4 = (const float4*)(smem + SM_SPB);
            float4* sg = (float4*)(out + (size_t)BATCH_TOT * NDIM + (rowBase + m0) * NDIM);
            #pragma unroll
            for (int i = 0; i < 16; i++) {
                int idx = ptid + i * 64;          // 0..1023 float4 within pair's 32 rows
                int r = m0 + (idx >> 5), c4 = idx & 31;
                float q = quad[r];
                float4 s = spb4[c4];
                sg[idx] = make_float4(q + s.x, q + s.y, q + s.z, q + s.w);
            }
        }
        bar_pair(pair + 1);                   // pair-scoped: safe to overwrite xh/xl/quad
    }
}

extern "C" void kernel_launch(void* const* d_in, const int* in_sizes, int n_in,
                              void* d_out, int out_size)
{
    const float* x       = (const float*)d_in[0];
    const float* w_mu    = (const float*)d_in[1];
    const float* w_sigma = (const float*)d_in[2];
    const float* b_mu    = (const float*)d_in[3];
    const float* b_sigma = (const float*)d_in[4];
    float* out = (float*)d_out;

    int dev = 0, sms = 148;
    cudaGetDevice(&dev);
    cudaDeviceGetAttribute(&sms, cudaDevAttrMultiProcessorCount, dev);
    int grid = 2 * sms;
    if (grid > NCHUNKS) grid = NCHUNKS;

    cudaFuncSetAttribute(fused_kernel, cudaFuncAttributeMaxDynamicSharedMemorySize, SM_TOTAL);

    fused_kernel<<<grid, 128, SM_TOTAL>>>(x, w_mu, w_sigma, b_mu, b_sigma, out,
                                          out + (size_t)out_size - 1);
}

// round 17
// speedup vs baseline: 1.6175x; 1.0391x over previous
#include <cuda_runtime.h>
#include <cuda_bf16.h>
#include <cstdint>

#define BATCH_TOT 524288
#define KDIM 128
#define NDIM 128
#define NTILES ((BATCH_TOT / 32) * 2)      // 32768 warp tiles of 32 rows x 64 cols

// W tiles: bf16, row pitch 272 bytes (17 x 16B) -> conflict-free ldmatrix
#define TPITCH 272
#define WTILE_BYTES (128 * TPITCH)         // 34816

// smem layout (bytes): only W + params. ~71 KB -> 2 CTAs/SM easily
#define SM_WH   0
#define SM_WL   (SM_WH + WTILE_BYTES)
#define SM_SPW  (SM_WL + WTILE_BYTES)      // 128 f32
#define SM_SPB  (SM_SPW + 512)             // 128 f32
#define SM_BMU  (SM_SPB + 512)             // 128 f32
#define SM_RED  (SM_BMU + 512)             // 4 f32
#define SM_TOTAL (SM_RED + 64)

__device__ __forceinline__ uint32_t smem_u32(const void* p) {
    uint32_t a;
    asm("{ .reg .u64 t; cvta.to.shared.u64 t, %1; cvt.u32.u64 %0, t; }" : "=r"(a) : "l"(p));
    return a;
}
__device__ __forceinline__ void ldsm_x4(uint32_t& r0, uint32_t& r1, uint32_t& r2, uint32_t& r3,
                                        uint32_t addr) {
    asm volatile("ldmatrix.sync.aligned.m8n8.x4.shared.b16 {%0,%1,%2,%3}, [%4];"
                 : "=r"(r0), "=r"(r1), "=r"(r2), "=r"(r3) : "r"(addr));
}
__device__ __forceinline__ void mma_bf16(float* c, const uint32_t* a, uint32_t b0, uint32_t b1) {
    asm volatile(
        "mma.sync.aligned.m16n8k16.row.col.f32.bf16.bf16.f32 "
        "{%0,%1,%2,%3}, {%4,%5,%6,%7}, {%8,%9}, {%0,%1,%2,%3};"
        : "+f"(c[0]), "+f"(c[1]), "+f"(c[2]), "+f"(c[3])
        : "r"(a[0]), "r"(a[1]), "r"(a[2]), "r"(a[3]), "r"(b0), "r"(b1));
}
// pack two floats as bf16x2 (low = first)
__device__ __forceinline__ uint32_t pack_hi(float a, float b) {
    __nv_bfloat16 h0 = __float2bfloat16(a), h1 = __float2bfloat16(b);
    return ((uint32_t)__bfloat16_as_ushort(h1) << 16) | __bfloat16_as_ushort(h0);
}
__device__ __forceinline__ uint32_t pack_lo(float a, float b) {
    __nv_bfloat16 h0 = __float2bfloat16(a), h1 = __float2bfloat16(b);
    float r0 = a - __bfloat162float(h0), r1 = b - __bfloat162float(h1);
    __nv_bfloat16 l0 = __float2bfloat16(r0), l1 = __float2bfloat16(r1);
    return ((uint32_t)__bfloat16_as_ushort(l1) << 16) | __bfloat16_as_ushort(l0);
}

// load this thread's A-fragment source floats for one 32(row)x16(k) step directly from x
// d[2j]   = x[rows+g+8j][c .. c+1]
// d[2j+1] = x[rows+g+8j][c+8 .. c+9]
__device__ __forceinline__ void load8(float2 d[8], const float* __restrict__ x,
                                      size_t rows, int g, int c) {
    #pragma unroll
    for (int j = 0; j < 4; j++) {
        const float* p = x + (rows + (size_t)(g + 8 * j)) * KDIM + c;
        d[2 * j]     = *(const float2*)(p);
        d[2 * j + 1] = *(const float2*)(p + 8);
    }
}

// ---------- single fused persistent kernel: barrier-free warp pipelines ----------
__global__ __launch_bounds__(128, 2)
void fused_kernel(const float* __restrict__ x, const float* __restrict__ w_mu,
                  const float* __restrict__ w_sigma, const float* __restrict__ b_mu,
                  const float* __restrict__ b_sigma, float* __restrict__ out,
                  float* __restrict__ out_kl)
{
    extern __shared__ __align__(16) unsigned char smem[];
    const uint32_t sbase = smem_u32(smem);
    const int tid = threadIdx.x, wid = tid >> 5, lane = tid & 31;
    const int g = lane >> 2, tig = lane & 3;

    // ---- one-time: softplus params + b_mu ----
    if (tid < 128) {
        float spw = log1pf(expf(w_sigma[tid]));
        ((float*)(smem + SM_SPW))[tid] = spw;
        ((float*)(smem + SM_SPB))[tid] = log1pf(expf(b_sigma[tid]));
        ((float*)(smem + SM_BMU))[tid] = b_mu[tid];
    }

    // ---- one-time: split W -> bf16 hi/lo into smem; accumulate |w| for KL ----
    float wabs = 0.f;
    #pragma unroll
    for (int i = 0; i < 128; i++) {
        int idx = tid + i * 128;             // idx = k*128 + n
        float w = w_mu[idx];
        wabs += fabsf(w);
        int k = idx >> 7, n = idx & 127;
        __nv_bfloat16 hi = __float2bfloat16(w);
        __nv_bfloat16 lo = __float2bfloat16(w - __bfloat162float(hi));
        int off = n * TPITCH + k * 2;        // B[n][k] = W[k][n]
        *(__nv_bfloat16*)(smem + SM_WH + off) = hi;
        *(__nv_bfloat16*)(smem + SM_WL + off) = lo;
    }
    if (blockIdx.x == 0) {
        #pragma unroll
        for (int o = 16; o > 0; o >>= 1) wabs += __shfl_xor_sync(0xffffffffu, wabs, o);
        if (lane == 0) ((float*)(smem + SM_RED))[wid] = wabs;
        __syncthreads();
        if (tid == 0) {
            const float* red = (const float*)(smem + SM_RED);
            const float* spw = (const float*)(smem + SM_SPW);
            float s = red[0] + red[1] + red[2] + red[3];
            float t = 0.f;
            #pragma unroll
            for (int j = 0; j < 128; j++) t += logf(spw[j]) - spw[j];
            out_kl[0] = -0.5f * (t - s);
        }
    }
    __syncthreads();                         // W + params visible; last sync in kernel

    const float* spw_s = (const float*)(smem + SM_SPW);
    const float* spb_s = (const float*)(smem + SM_SPB);
    const float* bmu_s = (const float*)(smem + SM_BMU);

    const int warpGlobal = blockIdx.x * 4 + wid;
    const int step = gridDim.x * 4;

    // B-side ldmatrix lane address (n0 added per tile)
    const uint32_t b_lane0 = sbase + (uint32_t)(((lane >> 4) * 8 + (lane & 7)) * TPITCH +
                                                ((lane >> 3) & 1) * 16);

    // prefetch kc=0 of first tile
    float2 nxt[8];
    if (warpGlobal < NTILES)
        load8(nxt, x, (size_t)(warpGlobal >> 1) * 32, g, tig * 2);

    for (int t = warpGlobal; t < NTILES; t += step) {
        const size_t rows = (size_t)(t >> 1) * 32;
        const int n0 = (t & 1) * 64;
        const uint32_t b_lane = b_lane0 + (uint32_t)(n0 * TPITCH);

        float acc[2][4][2][4];               // [mi][ni][h][4]
        #pragma unroll
        for (int mi = 0; mi < 2; mi++)
            #pragma unroll
            for (int ni = 0; ni < 4; ni++)
                #pragma unroll
                for (int h = 0; h < 2; h++)
                    #pragma unroll
                    for (int j = 0; j < 4; j++) acc[mi][ni][h][j] = 0.f;
        float qp[4] = {0.f, 0.f, 0.f, 0.f};  // quad partials for rows g+8j

        #pragma unroll
        for (int kc = 0; kc < 8; kc++) {
            // consume prefetched x
            float2 cur[8];
            #pragma unroll
            for (int i = 0; i < 8; i++) cur[i] = nxt[i];

            // issue next prefetch (next kc, or kc0 of next tile)
            if (kc < 7) {
                load8(nxt, x, rows, g, tig * 2 + (kc + 1) * 16);
            } else {
                int tn = t + step;
                if (tn < NTILES)
                    load8(nxt, x, (size_t)(tn >> 1) * 32, g, tig * 2);
            }

            const int c = tig * 2 + kc * 16;
            // quad partials
            {
                float2 w0 = *(const float2*)(spw_s + c);
                float2 w1 = *(const float2*)(spw_s + c + 8);
                #pragma unroll
                for (int j = 0; j < 4; j++) {
                    qp[j] = fmaf(cur[2 * j].x * cur[2 * j].x, w0.x, qp[j]);
                    qp[j] = fmaf(cur[2 * j].y * cur[2 * j].y, w0.y, qp[j]);
                    qp[j] = fmaf(cur[2 * j + 1].x * cur[2 * j + 1].x, w1.x, qp[j]);
                    qp[j] = fmaf(cur[2 * j + 1].y * cur[2 * j + 1].y, w1.y, qp[j]);
                }
            }
            // convert to A fragments (hi + lo)
            uint32_t ah[2][4], al[2][4];
            #pragma unroll
            for (int mi = 0; mi < 2; mi++) {
                const float2* cc = cur + mi * 4;
                ah[mi][0] = pack_hi(cc[0].x, cc[0].y);   // row g(+16mi),   cols c,c+1
                ah[mi][1] = pack_hi(cc[2].x, cc[2].y);   // row g+8(+16mi), cols c,c+1
                ah[mi][2] = pack_hi(cc[1].x, cc[1].y);   // row g(+16mi),   cols c+8,c+9
                ah[mi][3] = pack_hi(cc[3].x, cc[3].y);   // row g+8(+16mi), cols c+8,c+9
                al[mi][0] = pack_lo(cc[0].x, cc[0].y);
                al[mi][1] = pack_lo(cc[2].x, cc[2].y);
                al[mi][2] = pack_lo(cc[1].x, cc[1].y);
                al[mi][3] = pack_lo(cc[3].x, cc[3].y);
            }

            // B fragments from smem + MMA
            const uint32_t ko = (uint32_t)(kc * 32);
            #pragma unroll
            for (int ni = 0; ni < 4; ni++) {
                uint32_t bh[4], bl[4];
                ldsm_x4(bh[0], bh[1], bh[2], bh[3], b_lane + SM_WH + ni * (16 * TPITCH) + ko);
                ldsm_x4(bl[0], bl[1], bl[2], bl[3], b_lane + SM_WL + ni * (16 * TPITCH) + ko);
                #pragma unroll
                for (int mi = 0; mi < 2; mi++) {
                    mma_bf16(acc[mi][ni][0], ah[mi], bh[0], bh[1]);  // xh*wh
                    mma_bf16(acc[mi][ni][1], ah[mi], bh[2], bh[3]);
                    mma_bf16(acc[mi][ni][0], al[mi], bh[0], bh[1]);  // xl*wh
                    mma_bf16(acc[mi][ni][1], al[mi], bh[2], bh[3]);
                    mma_bf16(acc[mi][ni][0], ah[mi], bl[0], bl[1]);  // xh*wl
                    mma_bf16(acc[mi][ni][1], ah[mi], bl[2], bl[3]);
                }
            }
        }

        // ---- mu epilogue: fragments -> global ----
        {
            float2 bm[8];
            #pragma unroll
            for (int u = 0; u < 8; u++)
                bm[u] = *(const float2*)(bmu_s + n0 + u * 8 + 2 * tig);
            #pragma unroll
            for (int mi = 0; mi < 2; mi++) {
                float* o0 = out + (rows + (size_t)(mi * 16 + g)) * NDIM + n0;
                float* o1 = o0 + 8 * NDIM;
                #pragma unroll
                for (int ni = 0; ni < 4; ni++)
                    #pragma unroll
                    for (int h = 0; h < 2; h++) {
                        const float* cfr = acc[mi][ni][h];
                        int col = ni * 16 + h * 8 + 2 * tig;
                        float2 b = bm[ni * 2 + h];
                        *(float2*)(o0 + col) = make_float2(cfr[0] + b.x, cfr[1] + b.y);
                        *(float2*)(o1 + col) = make_float2(cfr[2] + b.x, cfr[3] + b.y);
                    }
            }
        }

        // ---- sigma epilogue: reduce quad in tig group, write n-half for our 32 rows ----
        {
            #pragma unroll
            for (int j = 0; j < 4; j++) {
                qp[j] += __shfl_xor_sync(0xffffffffu, qp[j], 1);
                qp[j] += __shfl_xor_sync(0xffffffffu, qp[j], 2);
            }
            float4 sb[4];
            #pragma unroll
            for (int u = 0; u < 4; u++)
                sb[u] = *(const float4*)(spb_s + n0 + tig * 16 + u * 4);
            #pragma unroll
            for (int j = 0; j < 4; j++) {
                size_t r = rows + (size_t)(g + 8 * j);
                float q = qp[j];
                float4* sg = (float4*)(out + (size_t)BATCH_TOT * NDIM + r * NDIM + n0 + tig * 16);
                #pragma unroll
                for (int u = 0; u < 4; u++)
                    sg[u] = make_float4(q + sb[u].x, q + sb[u].y, q + sb[u].z, q + sb[u].w);
            }
        }
    }
}

extern "C" void kernel_launch(void* const* d_in, const int* in_sizes, int n_in,
                              void* d_out, int out_size)
{
    const float* x       = (const float*)d_in[0];
    const float* w_mu    = (const float*)d_in[1];
    const float* w_sigma = (const float*)d_in[2];
    const float* b_mu    = (const float*)d_in[3];
    const float* b_sigma = (const float*)d_in[4];
    float* out = (float*)d_out;

    int dev = 0, sms = 148;
    cudaGetDevice(&dev);
    cudaDeviceGetAttribute(&sms, cudaDevAttrMultiProcessorCount, dev);
    int grid = 2 * sms;

    cudaFuncSetAttribute(fused_kernel, cudaFuncAttributeMaxDynamicSharedMemorySize, SM_TOTAL);

    fused_kernel<<<grid, 128, SM_TOTAL>>>(x, w_mu, w_sigma, b_mu, b_sigma, out,
                                          out + (size_t)out_size - 1);
}